// round 16
// baseline (speedup 1.0000x reference)
#include <cuda_runtime.h>

#define VOCAB 128000
#define VOCAB4 (VOCAB / 4)
#define NT 1024
#define NFULL 31                    // 31*1024 = 31744 full iterations
#define NREM (VOCAB4 - NFULL * NT)  // 256 remainder lanes
#define PFB 8                       // prefetch distance in block-iterations
#define PFD (PFB * NT)              // = 8192 float4 = 128 KB
#define CAP 6144
#define SUBCAP 512
#define NEGV (-1000000000.0f)
#define FULLMASK 0xffffffffu

#define DYN_SMEM (CAP * 8 + 1024 * 4)   // buf + bidx + hist = 53248 bytes

__global__ __launch_bounds__(NT, 2)
void topk_topp_v15(const float* __restrict__ in, float* __restrict__ out) {
    extern __shared__ char dyn[];
    float* buf  = (float*)dyn;                  // CAP candidate values
    int*   bidx = (int*)(dyn + CAP * 4);        // CAP candidate indices
    int*   hist = (int*)(dyn + CAP * 8);        // 1024 bins

    __shared__ float warp2nd[32];
    __shared__ float warpmax[32];
    __shared__ float topbuf[SUBCAP];
    __shared__ float topsorted[50];
    __shared__ float e50[50];
    __shared__ int   s_cnt, s_scnt, s_b1;
    __shared__ float s_t0, s_M, s_thresh;

    const int tid  = threadIdx.x;
    const int lane = tid & 31;
    const int wid  = tid >> 5;
    const float* __restrict__ x = in  + (size_t)blockIdx.x * VOCAB;
    float* __restrict__ y       = out + (size_t)blockIdx.x * VOCAB;
    const float4* __restrict__ x4 = (const float4*)x;
    const bool pfer = ((tid & 7) == 0);       // 1 thread per 128B line prefetches

    // ---------- Phase 0: init + warm the first PFD lines ----------
    hist[tid] = 0;
    if (tid == 0) { s_cnt = 0; s_scnt = 0; s_b1 = 0; }
    if (tid < 50) topsorted[tid] = NEGV;
    if (pfer) {
#pragma unroll
        for (int k = 0; k < PFB; k++)
            asm volatile("prefetch.global.L2 [%0];" :: "l"(x4 + tid + k * NT));
    }

    // ---------- Phase 1: sample 8192 elems, per-warp top-2 (overlaps warmup) ----------
    const float4* __restrict__ xs = (const float4*)(x + wid * 4000);
    float4 sa = xs[lane * 2];
    float4 sb = xs[lane * 2 + 1];
    float sv[8] = {sa.x, sa.y, sa.z, sa.w, sb.x, sb.y, sb.z, sb.w};

    float lm = sv[0];
#pragma unroll
    for (int k = 1; k < 8; k++) lm = fmaxf(lm, sv[k]);
    float wm = lm;
#pragma unroll
    for (int off = 16; off > 0; off >>= 1)
        wm = fmaxf(wm, __shfl_xor_sync(FULLMASK, wm, off));
    unsigned bal = __ballot_sync(FULLMASK, lm == wm);
    if (lane == (__ffs(bal) - 1)) {
        bool done = false;
#pragma unroll
        for (int k = 0; k < 8; k++)
            if (!done && sv[k] == wm) { sv[k] = -3.4e38f; done = true; }
    }
    float lm2 = sv[0];
#pragma unroll
    for (int k = 1; k < 8; k++) lm2 = fmaxf(lm2, sv[k]);
    float wm2 = lm2;
#pragma unroll
    for (int off = 16; off > 0; off >>= 1)
        wm2 = fmaxf(wm2, __shfl_xor_sync(FULLMASK, wm2, off));
    if (lane == 0) { warpmax[wid] = wm; warp2nd[wid] = wm2; }
    __syncthreads();

    if (tid == 0) {
        // t0 = 7th-smallest warp-2nd-max: 26 warps contribute >= 2 samples >= t0
        // -> >= 52 row elements >= t0 -> t0 <= row's 50th largest
        // -> candidate set provably contains the top-50.
        float a[32];
        float M = warpmax[0];
        for (int w = 0; w < 32; w++) { a[w] = warp2nd[w]; M = fmaxf(M, warpmax[w]); }
        for (int k = 0; k < 7; k++) {
            int mi = k;
            for (int j = k + 1; j < 32; j++) if (a[j] < a[mi]) mi = j;
            float t = a[k]; a[k] = a[mi]; a[mi] = t;
        }
        s_t0 = a[6];
        s_M  = M;
    }
    __syncthreads();
    const float t0 = s_t0;
    const float M  = s_M;
    const float scale = (M > t0) ? (1023.0f / (M - t0)) : 0.0f;

    // ---------- Phase 2: fused streaming pass + deep L2 prefetch ----------
    float4* __restrict__ y4 = (float4*)y;

#define BODY(IDX)                                                                     \
    {                                                                                 \
        const int _i = (IDX);                                                         \
        if (pfer) {                                                                   \
            int _pf = _i + PFD;                                                       \
            _pf = (_pf < VOCAB4) ? _pf : (VOCAB4 - 8);                                \
            asm volatile("prefetch.global.L2 [%0];" :: "l"(x4 + _pf));                \
        }                                                                             \
        float4 v = __ldcs(&x4[_i]);                                                   \
        float4 w;                                                                     \
        w.x = (v.x >= t0) ? v.x : NEGV;                                               \
        w.y = (v.y >= t0) ? v.y : NEGV;                                               \
        w.z = (v.z >= t0) ? v.z : NEGV;                                               \
        w.w = (v.w >= t0) ? v.w : NEGV;                                               \
        __stcs(&y4[_i], w);                                                           \
        if (v.x >= t0) { int p = atomicAdd(&s_cnt, 1); if (p < CAP) { buf[p] = v.x;   \
            bidx[p] = 4 * _i;     int b = (int)((v.x - t0) * scale);                  \
            b = b < 0 ? 0 : (b > 1023 ? 1023 : b); atomicAdd(&hist[b], 1); } }        \
        if (v.y >= t0) { int p = atomicAdd(&s_cnt, 1); if (p < CAP) { buf[p] = v.y;   \
            bidx[p] = 4 * _i + 1; int b = (int)((v.y - t0) * scale);                  \
            b = b < 0 ? 0 : (b > 1023 ? 1023 : b); atomicAdd(&hist[b], 1); } }        \
        if (v.z >= t0) { int p = atomicAdd(&s_cnt, 1); if (p < CAP) { buf[p] = v.z;   \
            bidx[p] = 4 * _i + 2; int b = (int)((v.z - t0) * scale);                  \
            b = b < 0 ? 0 : (b > 1023 ? 1023 : b); atomicAdd(&hist[b], 1); } }        \
        if (v.w >= t0) { int p = atomicAdd(&s_cnt, 1); if (p < CAP) { buf[p] = v.w;   \
            bidx[p] = 4 * _i + 3; int b = (int)((v.w - t0) * scale);                  \
            b = b < 0 ? 0 : (b > 1023 ? 1023 : b); atomicAdd(&hist[b], 1); } }        \
    }

#pragma unroll 2
    for (int it = 0; it < NFULL; it++)
        BODY(tid + it * NT)
    if (tid < NREM)
        BODY(tid + NFULL * NT)
#undef BODY

    __syncthreads();
    int cnt = s_cnt; if (cnt > CAP) cnt = CAP;

    // ---------- Phase 4: B1 = largest bin with suffix count >= 50 (warp 0) ----------
    if (wid == 0) {
        int c = 0;
        for (int j = 0; j < 32; j++) c += hist[lane * 32 + j];
        int s = c;
#pragma unroll
        for (int off = 1; off < 32; off <<= 1) {
            int t = __shfl_down_sync(FULLMASK, s, off);
            if (lane + off < 32) s += t;
        }
        unsigned bb = __ballot_sync(FULLMASK, (s >= 50) && (s - c < 50));
        if (bb) {
            int L = __ffs(bb) - 1;
            if (lane == L) {
                int acc = s - c;
                int B1 = L * 32;
                for (int j = 31; j >= 0; j--) {
                    acc += hist[L * 32 + j];
                    if (acc >= 50) { B1 = L * 32 + j; break; }
                }
                s_b1 = B1;
            }
        }
    }
    __syncthreads();
    const int B1 = s_b1;

    // ---------- Phase 5: sub-candidates (bin >= B1) ----------
    for (int i = tid; i < cnt; i += NT) {
        float v = buf[i];
        int b = (int)((v - t0) * scale);
        b = b < 0 ? 0 : (b > 1023 ? 1023 : b);
        if (b >= B1) { int p = atomicAdd(&s_scnt, 1); if (p < SUBCAP) topbuf[p] = v; }
    }
    __syncthreads();
    int sn = s_scnt; if (sn > SUBCAP) sn = SUBCAP;

    // ---------- Phase 6: rank-sort, keep top 50 descending ----------
    for (int i = tid; i < sn; i += NT) {
        float vi = topbuf[i];
        int r = 0;
        for (int j = 0; j < sn; j++) {
            float vj = topbuf[j];
            r += (vj > vi) || (vj == vi && j < i);
        }
        if (r < 50) topsorted[r] = vi;
    }
    __syncthreads();

    // ---------- Phase 7: softmax over top-50 (parallel exp) + nucleus cutoff ----------
    if (tid < 50) e50[tid] = expf(topsorted[tid] - topsorted[0]);
    __syncthreads();
    if (tid == 0) {
        float S = 0.0f;
        for (int i = 0; i < 50; i++) S += e50[i];
        float inv = 1.0f / S;
        float cum = e50[0] * inv;
        int m = 1;
        for (int i = 1; i < 50; i++) {
            if (cum <= 0.9f) m++;
            cum += e50[i] * inv;
        }
        s_thresh = topsorted[m - 1];
    }
    __syncthreads();

    // ---------- Phase 8: scatter fixup of failed candidates ----------
    const float t = s_thresh;
    for (int i = tid; i < cnt; i += NT)
        if (buf[i] < t) y[bidx[i]] = NEGV;
}

extern "C" void kernel_launch(void* const* d_in, const int* in_sizes, int n_in,
                              void* d_out, int out_size) {
    const float* logits = (const float*)d_in[0];
    float* out = (float*)d_out;
    const int rows = out_size / VOCAB;  // 256
    cudaFuncSetAttribute(topk_topp_v15,
                         cudaFuncAttributeMaxDynamicSharedMemorySize, DYN_SMEM);
    topk_topp_v15<<<rows, NT, DYN_SMEM>>>(logits, out);
}